// round 15
// baseline (speedup 1.0000x reference)
#include <cuda_runtime.h>
#include <cuda_bf16.h>
#include <cuda_fp16.h>
#include <math.h>
#include <stdint.h>

#define TSEQ 2048
#define BATCH 2
#define CDIM 2048
#define NH 16
#define NKV 4
#define HD 128
#define MROWS (BATCH*TSEQ)          // 4096
#define KVDIM (NKV*HD)              // 512
#define EPSF 1.1920928955078125e-07f

// ---------------- scratch (no allocation allowed) ----------------
__device__ float g_cos[TSEQ*(HD/2)];
__device__ float g_sin[TSEQ*(HD/2)];

// fp16 operands for projection GEMMs (A split hi/lo, W single-rounded)
__device__ __half g_xh[(size_t)MROWS*CDIM];
__device__ __half g_xl[(size_t)MROWS*CDIM];
__device__ __half g_Wqh[(size_t)CDIM*CDIM];
__device__ __half g_Wkh[(size_t)KVDIM*CDIM];
__device__ __half g_Wvh[(size_t)KVDIM*CDIM];
__device__ __half g_Woh[(size_t)CDIM*CDIM];
__device__ __half g_Ahh[(size_t)MROWS*CDIM];
__device__ __half g_All[(size_t)MROWS*CDIM];
// attention operands: Q/K bf16 3-term splits (score path), V single fp16
__device__ __nv_bfloat16 g_Qbh[(size_t)MROWS*CDIM];
__device__ __nv_bfloat16 g_Qbl[(size_t)MROWS*CDIM];
__device__ __nv_bfloat16 g_Kbh[(size_t)MROWS*KVDIM];
__device__ __nv_bfloat16 g_Kbl[(size_t)MROWS*KVDIM];
__device__ __half g_Vh[(size_t)MROWS*KVDIM];

// ---------------- small helpers ----------------
__device__ __forceinline__ uint32_t smem_u32(const void* p){
    uint32_t a;
    asm("{ .reg .u64 t; cvta.to.shared.u64 t, %1; cvt.u32.u64 %0, t; }" : "=r"(a) : "l"(p));
    return a;
}
__device__ __forceinline__ void cp16(uint32_t dst, const void* src){
    asm volatile("cp.async.cg.shared.global [%0], [%1], 16;" :: "r"(dst), "l"(src) : "memory");
}
#define CP_COMMIT() asm volatile("cp.async.commit_group;" ::: "memory")
#define CP_WAIT1()  asm volatile("cp.async.wait_group 1;" ::: "memory")

__device__ __forceinline__ void mma_bf16(float* c, const uint32_t* a, uint32_t b0, uint32_t b1){
    asm volatile(
        "mma.sync.aligned.m16n8k16.row.col.f32.bf16.bf16.f32 "
        "{%0,%1,%2,%3}, {%4,%5,%6,%7}, {%8,%9}, {%0,%1,%2,%3};"
        : "+f"(c[0]), "+f"(c[1]), "+f"(c[2]), "+f"(c[3])
        : "r"(a[0]), "r"(a[1]), "r"(a[2]), "r"(a[3]), "r"(b0), "r"(b1));
}
__device__ __forceinline__ void mma_f16(float* c, const uint32_t* a, uint32_t b0, uint32_t b1){
    asm volatile(
        "mma.sync.aligned.m16n8k16.row.col.f32.f16.f16.f32 "
        "{%0,%1,%2,%3}, {%4,%5,%6,%7}, {%8,%9}, {%0,%1,%2,%3};"
        : "+f"(c[0]), "+f"(c[1]), "+f"(c[2]), "+f"(c[3])
        : "r"(a[0]), "r"(a[1]), "r"(a[2]), "r"(a[3]), "r"(b0), "r"(b1));
}
__device__ __forceinline__ uint32_t ld2x16(const void* p){
    return *(const uint32_t*)p;
}
// bf16 split of a float pair
__device__ __forceinline__ void split_pack2(float f0, float f1, uint32_t& hi, uint32_t& lo){
    __nv_bfloat16 h0 = __float2bfloat16(f0);
    __nv_bfloat16 h1 = __float2bfloat16(f1);
    __nv_bfloat16 r0 = __float2bfloat16(f0 - __bfloat162float(h0));
    __nv_bfloat16 r1 = __float2bfloat16(f1 - __bfloat162float(h1));
    __nv_bfloat162 hh(h0, h1), ll(r0, r1);
    hi = *(uint32_t*)&hh;
    lo = *(uint32_t*)&ll;
}
// fp16 split of a float pair
__device__ __forceinline__ void split_pack2h(float f0, float f1, uint32_t& hi, uint32_t& lo){
    __half h0 = __float2half(f0);
    __half h1 = __float2half(f1);
    __half r0 = __float2half(f0 - __half2float(h0));
    __half r1 = __float2half(f1 - __half2float(h1));
    __half2 hh(h0, h1), ll(r0, r1);
    hi = *(uint32_t*)&hh;
    lo = *(uint32_t*)&ll;
}

// ---------------- RoPE trig table ----------------
__global__ void fill_trig_kernel() {
    int i = blockIdx.x * blockDim.x + threadIdx.x;
    if (i >= TSEQ * 64) return;
    int t = i >> 6;
    int f = i & 63;
    double theta = exp(((double)(-2 * f) / 128.0) * log(10000.0));
    double ang = (double)t * theta;
    const double twopi = 6.283185307179586476925286766559;
    double k = rint(ang / twopi);
    float rf = (float)(ang - k * twopi);
    g_cos[i] = cosf(rf);
    g_sin[i] = sinf(rf);
}

// ---------------- fp32 -> fp16 hi/lo split ----------------
__global__ __launch_bounds__(256) void splith_kernel(
    const float* __restrict__ in, __half* __restrict__ hi,
    __half* __restrict__ lo, int n4)
{
    int i = blockIdx.x * blockDim.x + threadIdx.x;
    if (i >= n4) return;
    float4 v = ((const float4*)in)[i];
    uint32_t h0, l0, h1, l1;
    split_pack2h(v.x, v.y, h0, l0);
    split_pack2h(v.z, v.w, h1, l1);
    ((uint32_t*)hi)[2*i+0] = h0;
    ((uint32_t*)hi)[2*i+1] = h1;
    ((uint32_t*)lo)[2*i+0] = l0;
    ((uint32_t*)lo)[2*i+1] = l1;
}

// ---------------- fp32 -> fp16 round (weights) ----------------
__global__ __launch_bounds__(256) void roundh_kernel(
    const float* __restrict__ in, __half* __restrict__ out, int n4)
{
    int i = blockIdx.x * blockDim.x + threadIdx.x;
    if (i >= n4) return;
    float4 v = ((const float4*)in)[i];
    __half2 a(__float2half(v.x), __float2half(v.y));
    __half2 b(__float2half(v.z), __float2half(v.w));
    ((uint32_t*)out)[2*i+0] = *(uint32_t*)&a;
    ((uint32_t*)out)[2*i+1] = *(uint32_t*)&b;
}

// ---------------- GEMM tiling constants ----------------
#define BPAD 40
#define TEL (128*BPAD)
#define STAGE2_EL (3*TEL)              // Ah, Al, Bh
#define GEMM2_SMEM_BYTES (2*STAGE2_EL*2)   // 61440

// ------- Fused QKV projection + RMSNorm + RoPE epilogue --------------------
// grid (24, 32): ct 0..15 -> Q head ct; 16..19 -> K head ct-16; 20..23 -> V.
// Q/K epilogue: row sum-of-squares (quad shfl + cross-warp smem), RMSNorm,
// RoPE on adjacent accumulator pairs, bf16 hi/lo split store.
__global__ __launch_bounds__(256, 2) void qkv_gemm_kernel(const float* __restrict__ gain)
{
    extern __shared__ __half smh[];
    const int tid = threadIdx.x;
    const int wid = tid >> 5, lane = tid & 31;
    const int g = lane >> 2, t4 = lane & 3;
    const int wm = (wid >> 1) * 32;
    const int wn = (wid & 1) * 64;
    const int bm = blockIdx.y * 128;
    const int ct = blockIdx.x;
    const int K = CDIM;

    const __half* Bhp;
    int nloc, Nout, mode;       // mode: 0 Q, 1 K, 2 V
    if (ct < 16)      { Bhp = g_Wqh; nloc = ct * 128;        Nout = CDIM;  mode = 0; }
    else if (ct < 20) { Bhp = g_Wkh; nloc = (ct - 16) * 128; Nout = KVDIM; mode = 1; }
    else              { Bhp = g_Wvh; nloc = (ct - 20) * 128; Nout = KVDIM; mode = 2; }

    const uint32_t smb = smem_u32(smh);
    float acc[2][8][4];
#pragma unroll
    for (int i = 0; i < 2; i++)
#pragma unroll
        for (int j = 0; j < 8; j++)
#pragma unroll
            for (int q = 0; q < 4; q++) acc[i][j][q] = 0.f;

    const int nch = K / 32;

    auto issue_chunk = [&](int c, int st) {
        const int k0 = c * 32;
        const uint32_t so = (uint32_t)st * (STAGE2_EL * 2);
        const __half* srcs[3] = {
            g_xh + (size_t)bm * K + k0, g_xl + (size_t)bm * K + k0,
            Bhp + (size_t)nloc * K + k0 };
#pragma unroll
        for (int t = 0; t < 3; t++) {
#pragma unroll
            for (int p = 0; p < 2; p++) {
                int idx = tid + p * 256;
                int r = idx >> 2;
                int c8 = (idx & 3) * 8;
                cp16(smb + so + (uint32_t)(t * TEL + r * BPAD + c8) * 2u,
                     srcs[t] + (size_t)r * K + c8);
            }
        }
    };

    issue_chunk(0, 0); CP_COMMIT();
    issue_chunk(1, 1); CP_COMMIT();

    for (int c = 0; c < nch; c++) {
        CP_WAIT1();
        __syncthreads();
        const int st = c & 1;
        const __half* Ahs = smh + st * STAGE2_EL;
        const __half* Als = Ahs + TEL;
        const __half* Bhs = Als + TEL;

#pragma unroll
        for (int kk = 0; kk < 32; kk += 16) {
            uint32_t ah[2][4], al[2][4];
#pragma unroll
            for (int mt = 0; mt < 2; mt++) {
                const __half* ap = Ahs + (wm + mt * 16 + g) * BPAD + kk + 2 * t4;
                ah[mt][0] = ld2x16(ap);
                ah[mt][1] = ld2x16(ap + 8 * BPAD);
                ah[mt][2] = ld2x16(ap + 8);
                ah[mt][3] = ld2x16(ap + 8 * BPAD + 8);
                const __half* aq = Als + (wm + mt * 16 + g) * BPAD + kk + 2 * t4;
                al[mt][0] = ld2x16(aq);
                al[mt][1] = ld2x16(aq + 8 * BPAD);
                al[mt][2] = ld2x16(aq + 8);
                al[mt][3] = ld2x16(aq + 8 * BPAD + 8);
            }
#pragma unroll
            for (int nt = 0; nt < 8; nt++) {
                const __half* bp = Bhs + (wn + nt * 8 + g) * BPAD + kk + 2 * t4;
                uint32_t b0 = ld2x16(bp);
                uint32_t b1 = ld2x16(bp + 8);
                mma_f16(acc[0][nt], ah[0], b0, b1);
                mma_f16(acc[1][nt], ah[1], b0, b1);
                mma_f16(acc[0][nt], al[0], b0, b1);
                mma_f16(acc[1][nt], al[1], b0, b1);
            }
        }
        __syncthreads();
        if (c + 2 < nch) issue_chunk(c + 2, st);
        CP_COMMIT();
    }

    if (mode == 2) {
        // ---- V epilogue: fp16 round, direct store ----
#pragma unroll
        for (int mt = 0; mt < 2; mt++) {
            int r0 = bm + wm + mt * 16 + g;
#pragma unroll
            for (int nt = 0; nt < 8; nt++) {
                int col = nloc + wn + nt * 8 + 2 * t4;
                __half2 w0(__float2half(acc[mt][nt][0]), __float2half(acc[mt][nt][1]));
                __half2 w1(__float2half(acc[mt][nt][2]), __float2half(acc[mt][nt][3]));
                *(uint32_t*)(g_Vh + (size_t)r0 * Nout + col) = *(uint32_t*)&w0;
                *(uint32_t*)(g_Vh + (size_t)(r0 + 8) * Nout + col) = *(uint32_t*)&w1;
            }
        }
    } else {
        // ---- Q/K epilogue: RMSNorm + RoPE + bf16 hi/lo split ----
        __syncthreads();                      // smem tiles no longer needed
        float* sums = (float*)smh;            // [2][128]
#pragma unroll
        for (int mt = 0; mt < 2; mt++) {
            float p0 = 0.f, p1 = 0.f;
#pragma unroll
            for (int nt = 0; nt < 8; nt++) {
                p0 += acc[mt][nt][0] * acc[mt][nt][0] + acc[mt][nt][1] * acc[mt][nt][1];
                p1 += acc[mt][nt][2] * acc[mt][nt][2] + acc[mt][nt][3] * acc[mt][nt][3];
            }
            p0 += __shfl_xor_sync(0xffffffffu, p0, 1);
            p0 += __shfl_xor_sync(0xffffffffu, p0, 2);
            p1 += __shfl_xor_sync(0xffffffffu, p1, 1);
            p1 += __shfl_xor_sync(0xffffffffu, p1, 2);
            if (t4 == 0) {
                sums[(wid & 1) * 128 + wm + mt * 16 + g]     = p0;
                sums[(wid & 1) * 128 + wm + mt * 16 + g + 8] = p1;
            }
        }
        __syncthreads();

        const float gmul = (mode == 0) ? gain[ct] * 0.08838834764831845f : 1.0f;
        __nv_bfloat16* dsth = (mode == 0) ? g_Qbh : g_Kbh;
        __nv_bfloat16* dstl = (mode == 0) ? g_Qbl : g_Kbl;
#pragma unroll
        for (int mt = 0; mt < 2; mt++) {
#pragma unroll
            for (int rr = 0; rr < 2; rr++) {
                int lrow = wm + mt * 16 + g + rr * 8;
                int grow = bm + lrow;
                int t = grow & (TSEQ - 1);
                float ss = sums[lrow] + sums[128 + lrow];
                float gm = rsqrtf(ss * (1.0f / 128.0f) + EPSF) * gmul;
#pragma unroll
                for (int nt = 0; nt < 8; nt++) {
                    float xe = acc[mt][nt][rr * 2];
                    float xo = acc[mt][nt][rr * 2 + 1];
                    int d = ((wn + nt * 8) >> 1) + t4;
                    float c = g_cos[t * 64 + d];
                    float s = g_sin[t * 64 + d];
                    float re = (xe * c - xo * s) * gm;
                    float ro = (xe * s + xo * c) * gm;
                    uint32_t hi, lo;
                    split_pack2(re, ro, hi, lo);
                    int col = nloc + wn + nt * 8 + 2 * t4;
                    *(uint32_t*)(dsth + (size_t)grow * Nout + col) = hi;
                    *(uint32_t*)(dstl + (size_t)grow * Nout + col) = lo;
                }
            }
        }
    }
}

// ------- fp16 2-product GEMM (O projection): C = (Ah+Al) * Bh^T ------------
__global__ __launch_bounds__(256, 2) void f16_gemm2_kernel(
    const __half* __restrict__ Ahp, const __half* __restrict__ Alp,
    const __half* __restrict__ Bhp,
    float* __restrict__ C, int M, int N, int K)
{
    extern __shared__ __half smh[];
    const int tid = threadIdx.x;
    const int wid = tid >> 5, lane = tid & 31;
    const int g = lane >> 2, t4 = lane & 3;
    const int wm = (wid >> 1) * 32;
    const int wn = (wid & 1) * 64;
    const int bm = blockIdx.y * 128, bn = blockIdx.x * 128;

    const uint32_t smb = smem_u32(smh);
    float acc[2][8][4];
#pragma unroll
    for (int i = 0; i < 2; i++)
#pragma unroll
        for (int j = 0; j < 8; j++)
#pragma unroll
            for (int q = 0; q < 4; q++) acc[i][j][q] = 0.f;

    const int nch = K / 32;

    auto issue_chunk = [&](int c, int st) {
        const int k0 = c * 32;
        const uint32_t so = (uint32_t)st * (STAGE2_EL * 2);
        const __half* srcs[3] = {
            Ahp + (size_t)bm * K + k0, Alp + (size_t)bm * K + k0,
            Bhp + (size_t)bn * K + k0 };
#pragma unroll
        for (int t = 0; t < 3; t++) {
#pragma unroll
            for (int p = 0; p < 2; p++) {
                int idx = tid + p * 256;
                int r = idx >> 2;
                int c8 = (idx & 3) * 8;
                cp16(smb + so + (uint32_t)(t * TEL + r * BPAD + c8) * 2u,
                     srcs[t] + (size_t)r * K + c8);
            }
        }
    };

    issue_chunk(0, 0); CP_COMMIT();
    issue_chunk(1, 1); CP_COMMIT();

    for (int c = 0; c < nch; c++) {
        CP_WAIT1();
        __syncthreads();
        const int st = c & 1;
        const __half* Ahs = smh + st * STAGE2_EL;
        const __half* Als = Ahs + TEL;
        const __half* Bhs = Als + TEL;

#pragma unroll
        for (int kk = 0; kk < 32; kk += 16) {
            uint32_t ah[2][4], al[2][4];
#pragma unroll
            for (int mt = 0; mt < 2; mt++) {
                const __half* ap = Ahs + (wm + mt * 16 + g) * BPAD + kk + 2 * t4;
                ah[mt][0] = ld2x16(ap);
                ah[mt][1] = ld2x16(ap + 8 * BPAD);
                ah[mt][2] = ld2x16(ap + 8);
                ah[mt][3] = ld2x16(ap + 8 * BPAD + 8);
                const __half* aq = Als + (wm + mt * 16 + g) * BPAD + kk + 2 * t4;
                al[mt][0] = ld2x16(aq);
                al[mt][1] = ld2x16(aq + 8 * BPAD);
                al[mt][2] = ld2x16(aq + 8);
                al[mt][3] = ld2x16(aq + 8 * BPAD + 8);
            }
#pragma unroll
            for (int nt = 0; nt < 8; nt++) {
                const __half* bp = Bhs + (wn + nt * 8 + g) * BPAD + kk + 2 * t4;
                uint32_t b0 = ld2x16(bp);
                uint32_t b1 = ld2x16(bp + 8);
                mma_f16(acc[0][nt], ah[0], b0, b1);
                mma_f16(acc[1][nt], ah[1], b0, b1);
                mma_f16(acc[0][nt], al[0], b0, b1);
                mma_f16(acc[1][nt], al[1], b0, b1);
            }
        }
        __syncthreads();
        if (c + 2 < nch) issue_chunk(c + 2, st);
        CP_COMMIT();
    }

#pragma unroll
    for (int mt = 0; mt < 2; mt++) {
        int r0 = bm + wm + mt * 16 + g;
#pragma unroll
        for (int nt = 0; nt < 8; nt++) {
            int col = bn + wn + nt * 8 + 2 * t4;
            float2 w0 = make_float2(acc[mt][nt][0], acc[mt][nt][1]);
            float2 w1 = make_float2(acc[mt][nt][2], acc[mt][nt][3]);
            *(float2*)(C + (size_t)r0 * N + col) = w0;
            *(float2*)(C + (size_t)(r0 + 8) * N + col) = w1;
        }
    }
}

// -------- Tensor-core flash attention, causal, GQA ------------------------
// S: bf16 3-term.  PV: fp16 2-product (P split, V single fp16).
#define KPAD 136
#define VTPAD 70
#define ATT_Q_EL (64*KPAD)
#define ATT_VT_EL (128*VTPAD)
#define ATT_SMEM_BYTES ((4*ATT_Q_EL)*2 + ATT_VT_EL*2)   // 87552

__global__ __launch_bounds__(128, 2) void attn_tc_kernel() {
    extern __shared__ __nv_bfloat16 sma[];
    __nv_bfloat16* Qh  = sma;
    __nv_bfloat16* Ql  = Qh + ATT_Q_EL;
    __nv_bfloat16* Kh  = Ql + ATT_Q_EL;
    __nv_bfloat16* Kl  = Kh + ATT_Q_EL;
    __half*        Vt  = (__half*)(Kl + ATT_Q_EL);

    const int qt = (int)(gridDim.x - 1u - blockIdx.x);   // long CTAs first
    const int h = blockIdx.y, b = blockIdx.z;
    const int kvh = h >> 2;
    const int tid = threadIdx.x, wid = tid >> 5, lane = tid & 31;
    const int g = lane >> 2, t4 = lane & 3;
    const int q0 = qt * 64, wq = wid * 16;

    const __nv_bfloat16* Qhb = g_Qbh + ((size_t)(b * TSEQ + q0)) * CDIM + h * HD;
    const __nv_bfloat16* Qlb = g_Qbl + ((size_t)(b * TSEQ + q0)) * CDIM + h * HD;
    const __nv_bfloat16* Khb = g_Kbh + ((size_t)b * TSEQ) * KVDIM + kvh * HD;
    const __nv_bfloat16* Klb = g_Kbl + ((size_t)b * TSEQ) * KVDIM + kvh * HD;
    const __half*        Vhb = g_Vh  + ((size_t)b * TSEQ) * KVDIM + kvh * HD;

    for (int f = tid; f < 1024; f += 128) {
        int r = f >> 4, c8 = (f & 15) * 8;
        *(uint4*)(Qh + r * KPAD + c8) = *(const uint4*)(Qhb + (size_t)r * CDIM + c8);
        *(uint4*)(Ql + r * KPAD + c8) = *(const uint4*)(Qlb + (size_t)r * CDIM + c8);
    }

    float o[16][4];
#pragma unroll
    for (int i = 0; i < 16; i++)
#pragma unroll
        for (int j = 0; j < 4; j++) o[i][j] = 0.f;
    float m0 = -1e30f, m1 = -1e30f, l0 = 0.f, l1 = 0.f;

    for (int kt = 0; kt <= qt; kt++) {
        const int k0 = kt * 64;
        __syncthreads();
        for (int f = tid; f < 1024; f += 128) {
            int r = f >> 4, c8 = (f & 15) * 8;
            *(uint4*)(Kh + r * KPAD + c8) =
                *(const uint4*)(Khb + (size_t)(k0 + r) * KVDIM + c8);
            *(uint4*)(Kl + r * KPAD + c8) =
                *(const uint4*)(Klb + (size_t)(k0 + r) * KVDIM + c8);
        }
        for (int f = tid; f < 1024; f += 128) {
            int r = f >> 4, c8 = (f & 15) * 8;
            uint4 vh = *(const uint4*)(Vhb + (size_t)(k0 + r) * KVDIM + c8);
            __half th[8];
            *(uint4*)th = vh;
#pragma unroll
            for (int j = 0; j < 8; j++)
                Vt[(c8 + j) * VTPAD + r] = th[j];
        }
        __syncthreads();

        // ---- S = Q K^T (3-term split, fp32 accum) ----
        float s[8][4];
#pragma unroll
        for (int i = 0; i < 8; i++)
#pragma unroll
            for (int j = 0; j < 4; j++) s[i][j] = 0.f;

#pragma unroll
        for (int kk = 0; kk < 128; kk += 16) {
            uint32_t ah[4], al[4];
            const __nv_bfloat16* ap = Qh + (wq + g) * KPAD + kk + 2 * t4;
            ah[0] = ld2x16(ap);
            ah[1] = ld2x16(ap + 8 * KPAD);
            ah[2] = ld2x16(ap + 8);
            ah[3] = ld2x16(ap + 8 * KPAD + 8);
            const __nv_bfloat16* aq = Ql + (wq + g) * KPAD + kk + 2 * t4;
            al[0] = ld2x16(aq);
            al[1] = ld2x16(aq + 8 * KPAD);
            al[2] = ld2x16(aq + 8);
            al[3] = ld2x16(aq + 8 * KPAD + 8);
#pragma unroll
            for (int nt = 0; nt < 8; nt++) {
                const __nv_bfloat16* bp = Kh + (nt * 8 + g) * KPAD + kk + 2 * t4;
                uint32_t b0h = ld2x16(bp), b1h = ld2x16(bp + 8);
                const __nv_bfloat16* bq = Kl + (nt * 8 + g) * KPAD + kk + 2 * t4;
                uint32_t b0l = ld2x16(bq), b1l = ld2x16(bq + 8);
                mma_bf16(s[nt], ah, b0h, b1h);
                mma_bf16(s[nt], ah, b0l, b1l);
                mma_bf16(s[nt], al, b0h, b1h);
            }
        }

        // ---- causal mask on diagonal tile ----
        if (kt == qt) {
            int qr0 = q0 + wq + g, qr1 = qr0 + 8;
#pragma unroll
            for (int nt = 0; nt < 8; nt++) {
                int kc = k0 + nt * 8 + 2 * t4;
                if (kc     > qr0) s[nt][0] = -1e30f;
                if (kc + 1 > qr0) s[nt][1] = -1e30f;
                if (kc     > qr1) s[nt][2] = -1e30f;
                if (kc + 1 > qr1) s[nt][3] = -1e30f;
            }
        }

        // ---- online softmax ----
        float mx0 = -1e30f, mx1 = -1e30f;
#pragma unroll
        for (int nt = 0; nt < 8; nt++) {
            mx0 = fmaxf(mx0, fmaxf(s[nt][0], s[nt][1]));
            mx1 = fmaxf(mx1, fmaxf(s[nt][2], s[nt][3]));
        }
        mx0 = fmaxf(mx0, __shfl_xor_sync(0xffffffffu, mx0, 1));
        mx0 = fmaxf(mx0, __shfl_xor_sync(0xffffffffu, mx0, 2));
        mx1 = fmaxf(mx1, __shfl_xor_sync(0xffffffffu, mx1, 1));
        mx1 = fmaxf(mx1, __shfl_xor_sync(0xffffffffu, mx1, 2));
        float mn0 = fmaxf(m0, mx0), mn1 = fmaxf(m1, mx1);
        float cr0 = __expf(m0 - mn0), cr1 = __expf(m1 - mn1);
        float sum0 = 0.f, sum1 = 0.f;
#pragma unroll
        for (int nt = 0; nt < 8; nt++) {
            s[nt][0] = __expf(s[nt][0] - mn0);
            s[nt][1] = __expf(s[nt][1] - mn0);
            s[nt][2] = __expf(s[nt][2] - mn1);
            s[nt][3] = __expf(s[nt][3] - mn1);
            sum0 += s[nt][0] + s[nt][1];
            sum1 += s[nt][2] + s[nt][3];
        }
        sum0 += __shfl_xor_sync(0xffffffffu, sum0, 1);
        sum0 += __shfl_xor_sync(0xffffffffu, sum0, 2);
        sum1 += __shfl_xor_sync(0xffffffffu, sum1, 1);
        sum1 += __shfl_xor_sync(0xffffffffu, sum1, 2);
        l0 = l0 * cr0 + sum0; m0 = mn0;
        l1 = l1 * cr1 + sum1; m1 = mn1;
#pragma unroll
        for (int nt = 0; nt < 16; nt++) {
            o[nt][0] *= cr0; o[nt][1] *= cr0;
            o[nt][2] *= cr1; o[nt][3] *= cr1;
        }

        // ---- O += P V (fp16 2-product; P fragments from S registers) ----
#pragma unroll
        for (int jp = 0; jp < 4; jp++) {
            uint32_t pah[4], pal[4];
            split_pack2h(s[2*jp  ][0], s[2*jp  ][1], pah[0], pal[0]);
            split_pack2h(s[2*jp  ][2], s[2*jp  ][3], pah[1], pal[1]);
            split_pack2h(s[2*jp+1][0], s[2*jp+1][1], pah[2], pal[2]);
            split_pack2h(s[2*jp+1][2], s[2*jp+1][3], pah[3], pal[3]);
#pragma unroll
            for (int nt = 0; nt < 16; nt++) {
                const __half* vp = Vt + (nt * 8 + g) * VTPAD + jp * 16 + 2 * t4;
                uint32_t v0 = ld2x16(vp), v1 = ld2x16(vp + 8);
                mma_f16(o[nt], pah, v0, v1);
                mma_f16(o[nt], pal, v0, v1);
            }
        }
    }

    // ---- epilogue: normalize, split to fp16 hi/lo, store ----
    float inv0 = 1.0f / l0, inv1 = 1.0f / l1;
    size_t row0 = (size_t)(b * TSEQ + q0 + wq + g) * CDIM + h * HD;
    size_t row1 = row0 + (size_t)8 * CDIM;
#pragma unroll
    for (int nt = 0; nt < 16; nt++) {
        int col = nt * 8 + 2 * t4;
        uint32_t hi, lo;
        split_pack2h(o[nt][0] * inv0, o[nt][1] * inv0, hi, lo);
        *(uint32_t*)(g_Ahh + row0 + col) = hi;
        *(uint32_t*)(g_All + row0 + col) = lo;
        split_pack2h(o[nt][2] * inv1, o[nt][3] * inv1, hi, lo);
        *(uint32_t*)(g_Ahh + row1 + col) = hi;
        *(uint32_t*)(g_All + row1 + col) = lo;
    }
}

// ---------------- launch ----------------
extern "C" void kernel_launch(void* const* d_in, const int* in_sizes, int n_in,
                              void* d_out, int out_size) {
    const float* x    = (const float*)d_in[0];
    const float* Wq   = (const float*)d_in[1];
    const float* Wk   = (const float*)d_in[2];
    const float* Wv   = (const float*)d_in[3];
    const float* Wo   = (const float*)d_in[4];
    const float* gain = (const float*)d_in[5];
    float* out = (float*)d_out;

    __half *xh, *xl, *wqh, *wkh, *wvh, *woh, *ah, *al;
    cudaGetSymbolAddress((void**)&xh, g_xh);   cudaGetSymbolAddress((void**)&xl, g_xl);
    cudaGetSymbolAddress((void**)&wqh, g_Wqh);
    cudaGetSymbolAddress((void**)&wkh, g_Wkh);
    cudaGetSymbolAddress((void**)&wvh, g_Wvh);
    cudaGetSymbolAddress((void**)&woh, g_Woh);
    cudaGetSymbolAddress((void**)&ah, g_Ahh);  cudaGetSymbolAddress((void**)&al, g_All);

    cudaFuncSetAttribute(qkv_gemm_kernel, cudaFuncAttributeMaxDynamicSharedMemorySize,
                         GEMM2_SMEM_BYTES);
    cudaFuncSetAttribute(f16_gemm2_kernel, cudaFuncAttributeMaxDynamicSharedMemorySize,
                         GEMM2_SMEM_BYTES);
    cudaFuncSetAttribute(attn_tc_kernel, cudaFuncAttributeMaxDynamicSharedMemorySize,
                         ATT_SMEM_BYTES);

    fill_trig_kernel<<<(TSEQ * 64 + 255) / 256, 256>>>();

    // operand prep
    splith_kernel<<<(MROWS*CDIM/4 + 255)/256, 256>>>(x, xh, xl, MROWS*CDIM/4);
    roundh_kernel<<<(CDIM*CDIM/4 + 255)/256, 256>>>(Wq, wqh, CDIM*CDIM/4);
    roundh_kernel<<<(KVDIM*CDIM/4 + 255)/256, 256>>>(Wk, wkh, KVDIM*CDIM/4);
    roundh_kernel<<<(KVDIM*CDIM/4 + 255)/256, 256>>>(Wv, wvh, KVDIM*CDIM/4);
    roundh_kernel<<<(CDIM*CDIM/4 + 255)/256, 256>>>(Wo, woh, CDIM*CDIM/4);

    // fused QKV projections + norm + rope (Q/K bf16 splits; V fp16 direct)
    dim3 gqkv(24, MROWS / 128);
    qkv_gemm_kernel<<<gqkv, 256, GEMM2_SMEM_BYTES>>>(gain);

    // tensor-core flash attention -> fp16 Ah/Al splits
    dim3 ga(TSEQ / 64, NH, BATCH);
    attn_tc_kernel<<<ga, 128, ATT_SMEM_BYTES>>>();

    // O projection (fp16 2-product)
    dim3 gq(CDIM / 128, MROWS / 128);
    f16_gemm2_kernel<<<gq, 256, GEMM2_SMEM_BYTES>>>(ah, al, woh, out, MROWS, CDIM, CDIM);
}

// round 16
// speedup vs baseline: 1.0941x; 1.0941x over previous
#include <cuda_runtime.h>
#include <cuda_bf16.h>
#include <cuda_fp16.h>
#include <math.h>
#include <stdint.h>

#define TSEQ 2048
#define BATCH 2
#define CDIM 2048
#define NH 16
#define NKV 4
#define HD 128
#define MROWS (BATCH*TSEQ)          // 4096
#define KVDIM (NKV*HD)              // 512
#define EPSF 1.1920928955078125e-07f

// ---------------- scratch (no allocation allowed) ----------------
__device__ float g_cos[TSEQ*(HD/2)];
__device__ float g_sin[TSEQ*(HD/2)];

// fp16 operands for projection GEMMs
__device__ __half g_xh[(size_t)MROWS*CDIM];
__device__ __half g_xl[(size_t)MROWS*CDIM];
__device__ __half g_Wqh[(size_t)CDIM*CDIM];
__device__ __half g_Wkh[(size_t)KVDIM*CDIM];
__device__ __half g_Wvh[(size_t)KVDIM*CDIM];
__device__ __half g_Woh[(size_t)CDIM*CDIM];
__device__ __half g_Ahh[(size_t)MROWS*CDIM];     // attention output (fp16)
// attention operands: Q/K bf16 3-term splits (score path), V single fp16
__device__ __nv_bfloat16 g_Qbh[(size_t)MROWS*CDIM];
__device__ __nv_bfloat16 g_Qbl[(size_t)MROWS*CDIM];
__device__ __nv_bfloat16 g_Kbh[(size_t)MROWS*KVDIM];
__device__ __nv_bfloat16 g_Kbl[(size_t)MROWS*KVDIM];
__device__ __half g_Vh[(size_t)MROWS*KVDIM];

// ---------------- small helpers ----------------
__device__ __forceinline__ uint32_t smem_u32(const void* p){
    uint32_t a;
    asm("{ .reg .u64 t; cvta.to.shared.u64 t, %1; cvt.u32.u64 %0, t; }" : "=r"(a) : "l"(p));
    return a;
}
__device__ __forceinline__ void cp16(uint32_t dst, const void* src){
    asm volatile("cp.async.cg.shared.global [%0], [%1], 16;" :: "r"(dst), "l"(src) : "memory");
}
#define CP_COMMIT() asm volatile("cp.async.commit_group;" ::: "memory")
#define CP_WAIT1()  asm volatile("cp.async.wait_group 1;" ::: "memory")

__device__ __forceinline__ void mma_bf16(float* c, const uint32_t* a, uint32_t b0, uint32_t b1){
    asm volatile(
        "mma.sync.aligned.m16n8k16.row.col.f32.bf16.bf16.f32 "
        "{%0,%1,%2,%3}, {%4,%5,%6,%7}, {%8,%9}, {%0,%1,%2,%3};"
        : "+f"(c[0]), "+f"(c[1]), "+f"(c[2]), "+f"(c[3])
        : "r"(a[0]), "r"(a[1]), "r"(a[2]), "r"(a[3]), "r"(b0), "r"(b1));
}
__device__ __forceinline__ void mma_f16(float* c, const uint32_t* a, uint32_t b0, uint32_t b1){
    asm volatile(
        "mma.sync.aligned.m16n8k16.row.col.f32.f16.f16.f32 "
        "{%0,%1,%2,%3}, {%4,%5,%6,%7}, {%8,%9}, {%0,%1,%2,%3};"
        : "+f"(c[0]), "+f"(c[1]), "+f"(c[2]), "+f"(c[3])
        : "r"(a[0]), "r"(a[1]), "r"(a[2]), "r"(a[3]), "r"(b0), "r"(b1));
}
__device__ __forceinline__ uint32_t ld2x16(const void* p){
    return *(const uint32_t*)p;
}
// bf16 split of a float pair
__device__ __forceinline__ void split_pack2(float f0, float f1, uint32_t& hi, uint32_t& lo){
    __nv_bfloat16 h0 = __float2bfloat16(f0);
    __nv_bfloat16 h1 = __float2bfloat16(f1);
    __nv_bfloat16 r0 = __float2bfloat16(f0 - __bfloat162float(h0));
    __nv_bfloat16 r1 = __float2bfloat16(f1 - __bfloat162float(h1));
    __nv_bfloat162 hh(h0, h1), ll(r0, r1);
    hi = *(uint32_t*)&hh;
    lo = *(uint32_t*)&ll;
}
// fp16 split of a float pair
__device__ __forceinline__ void split_pack2h(float f0, float f1, uint32_t& hi, uint32_t& lo){
    __half h0 = __float2half(f0);
    __half h1 = __float2half(f1);
    __half r0 = __float2half(f0 - __half2float(h0));
    __half r1 = __float2half(f1 - __half2float(h1));
    __half2 hh(h0, h1), ll(r0, r1);
    hi = *(uint32_t*)&hh;
    lo = *(uint32_t*)&ll;
}

// ---------------- RoPE trig table ----------------
__global__ void fill_trig_kernel() {
    int i = blockIdx.x * blockDim.x + threadIdx.x;
    if (i >= TSEQ * 64) return;
    int t = i >> 6;
    int f = i & 63;
    double theta = exp(((double)(-2 * f) / 128.0) * log(10000.0));
    double ang = (double)t * theta;
    const double twopi = 6.283185307179586476925286766559;
    double k = rint(ang / twopi);
    float rf = (float)(ang - k * twopi);
    g_cos[i] = cosf(rf);
    g_sin[i] = sinf(rf);
}

// ---------------- fp32 -> fp16 hi/lo split ----------------
__global__ __launch_bounds__(256) void splith_kernel(
    const float* __restrict__ in, __half* __restrict__ hi,
    __half* __restrict__ lo, int n4)
{
    int i = blockIdx.x * blockDim.x + threadIdx.x;
    if (i >= n4) return;
    float4 v = ((const float4*)in)[i];
    uint32_t h0, l0, h1, l1;
    split_pack2h(v.x, v.y, h0, l0);
    split_pack2h(v.z, v.w, h1, l1);
    ((uint32_t*)hi)[2*i+0] = h0;
    ((uint32_t*)hi)[2*i+1] = h1;
    ((uint32_t*)lo)[2*i+0] = l0;
    ((uint32_t*)lo)[2*i+1] = l1;
}

// ---------------- fp32 -> fp16 round (weights) ----------------
__global__ __launch_bounds__(256) void roundh_kernel(
    const float* __restrict__ in, __half* __restrict__ out, int n4)
{
    int i = blockIdx.x * blockDim.x + threadIdx.x;
    if (i >= n4) return;
    float4 v = ((const float4*)in)[i];
    __half2 a(__float2half(v.x), __float2half(v.y));
    __half2 b(__float2half(v.z), __float2half(v.w));
    ((uint32_t*)out)[2*i+0] = *(uint32_t*)&a;
    ((uint32_t*)out)[2*i+1] = *(uint32_t*)&b;
}

// ---------------- GEMM tiling constants ----------------
#define BPAD 40
#define TEL (128*BPAD)
#define STAGE2_EL (3*TEL)              // Ah, Al, Bh
#define GEMM2_SMEM_BYTES (2*STAGE2_EL*2)   // 61440
#define STAGE1_EL (2*TEL)              // Ah, Bh (single-product)
#define GEMM1_SMEM_BYTES (2*STAGE1_EL*2)   // 40960

// ------- Fused QKV projection + RMSNorm + RoPE epilogue --------------------
__global__ __launch_bounds__(256, 2) void qkv_gemm_kernel(const float* __restrict__ gain)
{
    extern __shared__ __half smh[];
    const int tid = threadIdx.x;
    const int wid = tid >> 5, lane = tid & 31;
    const int g = lane >> 2, t4 = lane & 3;
    const int wm = (wid >> 1) * 32;
    const int wn = (wid & 1) * 64;
    const int bm = blockIdx.y * 128;
    const int ct = blockIdx.x;
    const int K = CDIM;

    const __half* Bhp;
    int nloc, Nout, mode;       // mode: 0 Q, 1 K, 2 V
    if (ct < 16)      { Bhp = g_Wqh; nloc = ct * 128;        Nout = CDIM;  mode = 0; }
    else if (ct < 20) { Bhp = g_Wkh; nloc = (ct - 16) * 128; Nout = KVDIM; mode = 1; }
    else              { Bhp = g_Wvh; nloc = (ct - 20) * 128; Nout = KVDIM; mode = 2; }

    const uint32_t smb = smem_u32(smh);
    float acc[2][8][4];
#pragma unroll
    for (int i = 0; i < 2; i++)
#pragma unroll
        for (int j = 0; j < 8; j++)
#pragma unroll
            for (int q = 0; q < 4; q++) acc[i][j][q] = 0.f;

    const int nch = K / 32;

    auto issue_chunk = [&](int c, int st) {
        const int k0 = c * 32;
        const uint32_t so = (uint32_t)st * (STAGE2_EL * 2);
        const __half* srcs[3] = {
            g_xh + (size_t)bm * K + k0, g_xl + (size_t)bm * K + k0,
            Bhp + (size_t)nloc * K + k0 };
#pragma unroll
        for (int t = 0; t < 3; t++) {
#pragma unroll
            for (int p = 0; p < 2; p++) {
                int idx = tid + p * 256;
                int r = idx >> 2;
                int c8 = (idx & 3) * 8;
                cp16(smb + so + (uint32_t)(t * TEL + r * BPAD + c8) * 2u,
                     srcs[t] + (size_t)r * K + c8);
            }
        }
    };

    issue_chunk(0, 0); CP_COMMIT();
    issue_chunk(1, 1); CP_COMMIT();

    for (int c = 0; c < nch; c++) {
        CP_WAIT1();
        __syncthreads();
        const int st = c & 1;
        const __half* Ahs = smh + st * STAGE2_EL;
        const __half* Als = Ahs + TEL;
        const __half* Bhs = Als + TEL;

#pragma unroll
        for (int kk = 0; kk < 32; kk += 16) {
            uint32_t ah[2][4], al[2][4];
#pragma unroll
            for (int mt = 0; mt < 2; mt++) {
                const __half* ap = Ahs + (wm + mt * 16 + g) * BPAD + kk + 2 * t4;
                ah[mt][0] = ld2x16(ap);
                ah[mt][1] = ld2x16(ap + 8 * BPAD);
                ah[mt][2] = ld2x16(ap + 8);
                ah[mt][3] = ld2x16(ap + 8 * BPAD + 8);
                const __half* aq = Als + (wm + mt * 16 + g) * BPAD + kk + 2 * t4;
                al[mt][0] = ld2x16(aq);
                al[mt][1] = ld2x16(aq + 8 * BPAD);
                al[mt][2] = ld2x16(aq + 8);
                al[mt][3] = ld2x16(aq + 8 * BPAD + 8);
            }
#pragma unroll
            for (int nt = 0; nt < 8; nt++) {
                const __half* bp = Bhs + (wn + nt * 8 + g) * BPAD + kk + 2 * t4;
                uint32_t b0 = ld2x16(bp);
                uint32_t b1 = ld2x16(bp + 8);
                mma_f16(acc[0][nt], ah[0], b0, b1);
                mma_f16(acc[1][nt], ah[1], b0, b1);
                mma_f16(acc[0][nt], al[0], b0, b1);
                mma_f16(acc[1][nt], al[1], b0, b1);
            }
        }
        __syncthreads();
        if (c + 2 < nch) issue_chunk(c + 2, st);
        CP_COMMIT();
    }

    if (mode == 2) {
        // ---- V epilogue: fp16 round, direct store ----
#pragma unroll
        for (int mt = 0; mt < 2; mt++) {
            int r0 = bm + wm + mt * 16 + g;
#pragma unroll
            for (int nt = 0; nt < 8; nt++) {
                int col = nloc + wn + nt * 8 + 2 * t4;
                __half2 w0(__float2half(acc[mt][nt][0]), __float2half(acc[mt][nt][1]));
                __half2 w1(__float2half(acc[mt][nt][2]), __float2half(acc[mt][nt][3]));
                *(uint32_t*)(g_Vh + (size_t)r0 * Nout + col) = *(uint32_t*)&w0;
                *(uint32_t*)(g_Vh + (size_t)(r0 + 8) * Nout + col) = *(uint32_t*)&w1;
            }
        }
    } else {
        // ---- Q/K epilogue: RMSNorm + RoPE + bf16 hi/lo split ----
        __syncthreads();
        float* sums = (float*)smh;            // [2][128]
#pragma unroll
        for (int mt = 0; mt < 2; mt++) {
            float p0 = 0.f, p1 = 0.f;
#pragma unroll
            for (int nt = 0; nt < 8; nt++) {
                p0 += acc[mt][nt][0] * acc[mt][nt][0] + acc[mt][nt][1] * acc[mt][nt][1];
                p1 += acc[mt][nt][2] * acc[mt][nt][2] + acc[mt][nt][3] * acc[mt][nt][3];
            }
            p0 += __shfl_xor_sync(0xffffffffu, p0, 1);
            p0 += __shfl_xor_sync(0xffffffffu, p0, 2);
            p1 += __shfl_xor_sync(0xffffffffu, p1, 1);
            p1 += __shfl_xor_sync(0xffffffffu, p1, 2);
            if (t4 == 0) {
                sums[(wid & 1) * 128 + wm + mt * 16 + g]     = p0;
                sums[(wid & 1) * 128 + wm + mt * 16 + g + 8] = p1;
            }
        }
        __syncthreads();

        const float gmul = (mode == 0) ? gain[ct] * 0.08838834764831845f : 1.0f;
        __nv_bfloat16* dsth = (mode == 0) ? g_Qbh : g_Kbh;
        __nv_bfloat16* dstl = (mode == 0) ? g_Qbl : g_Kbl;
#pragma unroll
        for (int mt = 0; mt < 2; mt++) {
#pragma unroll
            for (int rr = 0; rr < 2; rr++) {
                int lrow = wm + mt * 16 + g + rr * 8;
                int grow = bm + lrow;
                int t = grow & (TSEQ - 1);
                float ss = sums[lrow] + sums[128 + lrow];
                float gm = rsqrtf(ss * (1.0f / 128.0f) + EPSF) * gmul;
#pragma unroll
                for (int nt = 0; nt < 8; nt++) {
                    float xe = acc[mt][nt][rr * 2];
                    float xo = acc[mt][nt][rr * 2 + 1];
                    int d = ((wn + nt * 8) >> 1) + t4;
                    float c = g_cos[t * 64 + d];
                    float s = g_sin[t * 64 + d];
                    float re = (xe * c - xo * s) * gm;
                    float ro = (xe * s + xo * c) * gm;
                    uint32_t hi, lo;
                    split_pack2(re, ro, hi, lo);
                    int col = nloc + wn + nt * 8 + 2 * t4;
                    *(uint32_t*)(dsth + (size_t)grow * Nout + col) = hi;
                    *(uint32_t*)(dstl + (size_t)grow * Nout + col) = lo;
                }
            }
        }
    }
}

// ------- fp16 single-product GEMM (O projection): C = Ah * Bh^T ------------
__global__ __launch_bounds__(256, 2) void f16_gemm1_kernel(
    const __half* __restrict__ Ahp, const __half* __restrict__ Bhp,
    float* __restrict__ C, int M, int N, int K)
{
    extern __shared__ __half smh[];
    const int tid = threadIdx.x;
    const int wid = tid >> 5, lane = tid & 31;
    const int g = lane >> 2, t4 = lane & 3;
    const int wm = (wid >> 1) * 32;
    const int wn = (wid & 1) * 64;
    const int bm = blockIdx.y * 128, bn = blockIdx.x * 128;

    const uint32_t smb = smem_u32(smh);
    float acc[2][8][4];
#pragma unroll
    for (int i = 0; i < 2; i++)
#pragma unroll
        for (int j = 0; j < 8; j++)
#pragma unroll
            for (int q = 0; q < 4; q++) acc[i][j][q] = 0.f;

    const int nch = K / 32;

    auto issue_chunk = [&](int c, int st) {
        const int k0 = c * 32;
        const uint32_t so = (uint32_t)st * (STAGE1_EL * 2);
        const __half* srcs[2] = {
            Ahp + (size_t)bm * K + k0, Bhp + (size_t)bn * K + k0 };
#pragma unroll
        for (int t = 0; t < 2; t++) {
#pragma unroll
            for (int p = 0; p < 2; p++) {
                int idx = tid + p * 256;
                int r = idx >> 2;
                int c8 = (idx & 3) * 8;
                cp16(smb + so + (uint32_t)(t * TEL + r * BPAD + c8) * 2u,
                     srcs[t] + (size_t)r * K + c8);
            }
        }
    };

    issue_chunk(0, 0); CP_COMMIT();
    issue_chunk(1, 1); CP_COMMIT();

    for (int c = 0; c < nch; c++) {
        CP_WAIT1();
        __syncthreads();
        const int st = c & 1;
        const __half* Ahs = smh + st * STAGE1_EL;
        const __half* Bhs = Ahs + TEL;

#pragma unroll
        for (int kk = 0; kk < 32; kk += 16) {
            uint32_t ah[2][4];
#pragma unroll
            for (int mt = 0; mt < 2; mt++) {
                const __half* ap = Ahs + (wm + mt * 16 + g) * BPAD + kk + 2 * t4;
                ah[mt][0] = ld2x16(ap);
                ah[mt][1] = ld2x16(ap + 8 * BPAD);
                ah[mt][2] = ld2x16(ap + 8);
                ah[mt][3] = ld2x16(ap + 8 * BPAD + 8);
            }
#pragma unroll
            for (int nt = 0; nt < 8; nt++) {
                const __half* bp = Bhs + (wn + nt * 8 + g) * BPAD + kk + 2 * t4;
                uint32_t b0 = ld2x16(bp);
                uint32_t b1 = ld2x16(bp + 8);
                mma_f16(acc[0][nt], ah[0], b0, b1);
                mma_f16(acc[1][nt], ah[1], b0, b1);
            }
        }
        __syncthreads();
        if (c + 2 < nch) issue_chunk(c + 2, st);
        CP_COMMIT();
    }

#pragma unroll
    for (int mt = 0; mt < 2; mt++) {
        int r0 = bm + wm + mt * 16 + g;
#pragma unroll
        for (int nt = 0; nt < 8; nt++) {
            int col = bn + wn + nt * 8 + 2 * t4;
            float2 w0 = make_float2(acc[mt][nt][0], acc[mt][nt][1]);
            float2 w1 = make_float2(acc[mt][nt][2], acc[mt][nt][3]);
            *(float2*)(C + (size_t)r0 * N + col) = w0;
            *(float2*)(C + (size_t)(r0 + 8) * N + col) = w1;
        }
    }
}

// -------- Tensor-core flash attention, causal, GQA ------------------------
// S: bf16 3-term.  PV: fp16 2-product (P split, V single fp16).
#define KPAD 136
#define VTPAD 70
#define ATT_Q_EL (64*KPAD)
#define ATT_VT_EL (128*VTPAD)
#define ATT_SMEM_BYTES ((4*ATT_Q_EL)*2 + ATT_VT_EL*2)   // 87552

__global__ __launch_bounds__(128, 2) void attn_tc_kernel() {
    extern __shared__ __nv_bfloat16 sma[];
    __nv_bfloat16* Qh  = sma;
    __nv_bfloat16* Ql  = Qh + ATT_Q_EL;
    __nv_bfloat16* Kh  = Ql + ATT_Q_EL;
    __nv_bfloat16* Kl  = Kh + ATT_Q_EL;
    __half*        Vt  = (__half*)(Kl + ATT_Q_EL);

    const int qt = (int)(gridDim.x - 1u - blockIdx.x);   // long CTAs first
    const int h = blockIdx.y, b = blockIdx.z;
    const int kvh = h >> 2;
    const int tid = threadIdx.x, wid = tid >> 5, lane = tid & 31;
    const int g = lane >> 2, t4 = lane & 3;
    const int q0 = qt * 64, wq = wid * 16;

    const __nv_bfloat16* Qhb = g_Qbh + ((size_t)(b * TSEQ + q0)) * CDIM + h * HD;
    const __nv_bfloat16* Qlb = g_Qbl + ((size_t)(b * TSEQ + q0)) * CDIM + h * HD;
    const __nv_bfloat16* Khb = g_Kbh + ((size_t)b * TSEQ) * KVDIM + kvh * HD;
    const __nv_bfloat16* Klb = g_Kbl + ((size_t)b * TSEQ) * KVDIM + kvh * HD;
    const __half*        Vhb = g_Vh  + ((size_t)b * TSEQ) * KVDIM + kvh * HD;

    for (int f = tid; f < 1024; f += 128) {
        int r = f >> 4, c8 = (f & 15) * 8;
        *(uint4*)(Qh + r * KPAD + c8) = *(const uint4*)(Qhb + (size_t)r * CDIM + c8);
        *(uint4*)(Ql + r * KPAD + c8) = *(const uint4*)(Qlb + (size_t)r * CDIM + c8);
    }

    float o[16][4];
#pragma unroll
    for (int i = 0; i < 16; i++)
#pragma unroll
        for (int j = 0; j < 4; j++) o[i][j] = 0.f;
    float m0 = -1e30f, m1 = -1e30f, l0 = 0.f, l1 = 0.f;

    for (int kt = 0; kt <= qt; kt++) {
        const int k0 = kt * 64;
        __syncthreads();
        for (int f = tid; f < 1024; f += 128) {
            int r = f >> 4, c8 = (f & 15) * 8;
            *(uint4*)(Kh + r * KPAD + c8) =
                *(const uint4*)(Khb + (size_t)(k0 + r) * KVDIM + c8);
            *(uint4*)(Kl + r * KPAD + c8) =
                *(const uint4*)(Klb + (size_t)(k0 + r) * KVDIM + c8);
        }
        for (int f = tid; f < 1024; f += 128) {
            int r = f >> 4, c8 = (f & 15) * 8;
            uint4 vh = *(const uint4*)(Vhb + (size_t)(k0 + r) * KVDIM + c8);
            __half th[8];
            *(uint4*)th = vh;
#pragma unroll
            for (int j = 0; j < 8; j++)
                Vt[(c8 + j) * VTPAD + r] = th[j];
        }
        __syncthreads();

        // ---- S = Q K^T (3-term split, fp32 accum) ----
        float s[8][4];
#pragma unroll
        for (int i = 0; i < 8; i++)
#pragma unroll
            for (int j = 0; j < 4; j++) s[i][j] = 0.f;

#pragma unroll
        for (int kk = 0; kk < 128; kk += 16) {
            uint32_t ah[4], al[4];
            const __nv_bfloat16* ap = Qh + (wq + g) * KPAD + kk + 2 * t4;
            ah[0] = ld2x16(ap);
            ah[1] = ld2x16(ap + 8 * KPAD);
            ah[2] = ld2x16(ap + 8);
            ah[3] = ld2x16(ap + 8 * KPAD + 8);
            const __nv_bfloat16* aq = Ql + (wq + g) * KPAD + kk + 2 * t4;
            al[0] = ld2x16(aq);
            al[1] = ld2x16(aq + 8 * KPAD);
            al[2] = ld2x16(aq + 8);
            al[3] = ld2x16(aq + 8 * KPAD + 8);
#pragma unroll
            for (int nt = 0; nt < 8; nt++) {
                const __nv_bfloat16* bp = Kh + (nt * 8 + g) * KPAD + kk + 2 * t4;
                uint32_t b0h = ld2x16(bp), b1h = ld2x16(bp + 8);
                const __nv_bfloat16* bq = Kl + (nt * 8 + g) * KPAD + kk + 2 * t4;
                uint32_t b0l = ld2x16(bq), b1l = ld2x16(bq + 8);
                mma_bf16(s[nt], ah, b0h, b1h);
                mma_bf16(s[nt], ah, b0l, b1l);
                mma_bf16(s[nt], al, b0h, b1h);
            }
        }

        // ---- causal mask on diagonal tile ----
        if (kt == qt) {
            int qr0 = q0 + wq + g, qr1 = qr0 + 8;
#pragma unroll
            for (int nt = 0; nt < 8; nt++) {
                int kc = k0 + nt * 8 + 2 * t4;
                if (kc     > qr0) s[nt][0] = -1e30f;
                if (kc + 1 > qr0) s[nt][1] = -1e30f;
                if (kc     > qr1) s[nt][2] = -1e30f;
                if (kc + 1 > qr1) s[nt][3] = -1e30f;
            }
        }

        // ---- online softmax ----
        float mx0 = -1e30f, mx1 = -1e30f;
#pragma unroll
        for (int nt = 0; nt < 8; nt++) {
            mx0 = fmaxf(mx0, fmaxf(s[nt][0], s[nt][1]));
            mx1 = fmaxf(mx1, fmaxf(s[nt][2], s[nt][3]));
        }
        mx0 = fmaxf(mx0, __shfl_xor_sync(0xffffffffu, mx0, 1));
        mx0 = fmaxf(mx0, __shfl_xor_sync(0xffffffffu, mx0, 2));
        mx1 = fmaxf(mx1, __shfl_xor_sync(0xffffffffu, mx1, 1));
        mx1 = fmaxf(mx1, __shfl_xor_sync(0xffffffffu, mx1, 2));
        float mn0 = fmaxf(m0, mx0), mn1 = fmaxf(m1, mx1);
        float cr0 = __expf(m0 - mn0), cr1 = __expf(m1 - mn1);
        float sum0 = 0.f, sum1 = 0.f;
#pragma unroll
        for (int nt = 0; nt < 8; nt++) {
            s[nt][0] = __expf(s[nt][0] - mn0);
            s[nt][1] = __expf(s[nt][1] - mn0);
            s[nt][2] = __expf(s[nt][2] - mn1);
            s[nt][3] = __expf(s[nt][3] - mn1);
            sum0 += s[nt][0] + s[nt][1];
            sum1 += s[nt][2] + s[nt][3];
        }
        sum0 += __shfl_xor_sync(0xffffffffu, sum0, 1);
        sum0 += __shfl_xor_sync(0xffffffffu, sum0, 2);
        sum1 += __shfl_xor_sync(0xffffffffu, sum1, 1);
        sum1 += __shfl_xor_sync(0xffffffffu, sum1, 2);
        l0 = l0 * cr0 + sum0; m0 = mn0;
        l1 = l1 * cr1 + sum1; m1 = mn1;
#pragma unroll
        for (int nt = 0; nt < 16; nt++) {
            o[nt][0] *= cr0; o[nt][1] *= cr0;
            o[nt][2] *= cr1; o[nt][3] *= cr1;
        }

        // ---- O += P V (fp16 2-product; P fragments from S registers) ----
#pragma unroll
        for (int jp = 0; jp < 4; jp++) {
            uint32_t pah[4], pal[4];
            split_pack2h(s[2*jp  ][0], s[2*jp  ][1], pah[0], pal[0]);
            split_pack2h(s[2*jp  ][2], s[2*jp  ][3], pah[1], pal[1]);
            split_pack2h(s[2*jp+1][0], s[2*jp+1][1], pah[2], pal[2]);
            split_pack2h(s[2*jp+1][2], s[2*jp+1][3], pah[3], pal[3]);
#pragma unroll
            for (int nt = 0; nt < 16; nt++) {
                const __half* vp = Vt + (nt * 8 + g) * VTPAD + jp * 16 + 2 * t4;
                uint32_t v0 = ld2x16(vp), v1 = ld2x16(vp + 8);
                mma_f16(o[nt], pah, v0, v1);
                mma_f16(o[nt], pal, v0, v1);
            }
        }
    }

    // ---- epilogue: normalize, round to fp16, store ----
    float inv0 = 1.0f / l0, inv1 = 1.0f / l1;
    size_t row0 = (size_t)(b * TSEQ + q0 + wq + g) * CDIM + h * HD;
    size_t row1 = row0 + (size_t)8 * CDIM;
#pragma unroll
    for (int nt = 0; nt < 16; nt++) {
        int col = nt * 8 + 2 * t4;
        __half2 w0(__float2half(o[nt][0] * inv0), __float2half(o[nt][1] * inv0));
        __half2 w1(__float2half(o[nt][2] * inv1), __float2half(o[nt][3] * inv1));
        *(uint32_t*)(g_Ahh + row0 + col) = *(uint32_t*)&w0;
        *(uint32_t*)(g_Ahh + row1 + col) = *(uint32_t*)&w1;
    }
}

// ---------------- launch ----------------
extern "C" void kernel_launch(void* const* d_in, const int* in_sizes, int n_in,
                              void* d_out, int out_size) {
    const float* x    = (const float*)d_in[0];
    const float* Wq   = (const float*)d_in[1];
    const float* Wk   = (const float*)d_in[2];
    const float* Wv   = (const float*)d_in[3];
    const float* Wo   = (const float*)d_in[4];
    const float* gain = (const float*)d_in[5];
    float* out = (float*)d_out;

    __half *xh, *xl, *wqh, *wkh, *wvh, *woh, *ah;
    cudaGetSymbolAddress((void**)&xh, g_xh);   cudaGetSymbolAddress((void**)&xl, g_xl);
    cudaGetSymbolAddress((void**)&wqh, g_Wqh);
    cudaGetSymbolAddress((void**)&wkh, g_Wkh);
    cudaGetSymbolAddress((void**)&wvh, g_Wvh);
    cudaGetSymbolAddress((void**)&woh, g_Woh);
    cudaGetSymbolAddress((void**)&ah, g_Ahh);

    cudaFuncSetAttribute(qkv_gemm_kernel, cudaFuncAttributeMaxDynamicSharedMemorySize,
                         GEMM2_SMEM_BYTES);
    cudaFuncSetAttribute(f16_gemm1_kernel, cudaFuncAttributeMaxDynamicSharedMemorySize,
                         GEMM1_SMEM_BYTES);
    cudaFuncSetAttribute(attn_tc_kernel, cudaFuncAttributeMaxDynamicSharedMemorySize,
                         ATT_SMEM_BYTES);

    fill_trig_kernel<<<(TSEQ * 64 + 255) / 256, 256>>>();

    // operand prep
    splith_kernel<<<(MROWS*CDIM/4 + 255)/256, 256>>>(x, xh, xl, MROWS*CDIM/4);
    roundh_kernel<<<(CDIM*CDIM/4 + 255)/256, 256>>>(Wq, wqh, CDIM*CDIM/4);
    roundh_kernel<<<(KVDIM*CDIM/4 + 255)/256, 256>>>(Wk, wkh, KVDIM*CDIM/4);
    roundh_kernel<<<(KVDIM*CDIM/4 + 255)/256, 256>>>(Wv, wvh, KVDIM*CDIM/4);
    roundh_kernel<<<(CDIM*CDIM/4 + 255)/256, 256>>>(Wo, woh, CDIM*CDIM/4);

    // fused QKV projections + norm + rope (Q/K bf16 splits; V fp16 direct)
    dim3 gqkv(24, MROWS / 128);
    qkv_gemm_kernel<<<gqkv, 256, GEMM2_SMEM_BYTES>>>(gain);

    // tensor-core flash attention -> fp16 A
    dim3 ga(TSEQ / 64, NH, BATCH);
    attn_tc_kernel<<<ga, 128, ATT_SMEM_BYTES>>>();

    // O projection (fp16 single-product)
    dim3 gq(CDIM / 128, MROWS / 128);
    f16_gemm1_kernel<<<gq, 256, GEMM1_SMEM_BYTES>>>(ah, woh, out, MROWS, CDIM, CDIM);
}

// round 17
// speedup vs baseline: 1.1227x; 1.0262x over previous
#include <cuda_runtime.h>
#include <cuda_bf16.h>
#include <cuda_fp16.h>
#include <math.h>
#include <stdint.h>

#define TSEQ 2048
#define BATCH 2
#define CDIM 2048
#define NH 16
#define NKV 4
#define HD 128
#define MROWS (BATCH*TSEQ)          // 4096
#define KVDIM (NKV*HD)              // 512
#define EPSF 1.1920928955078125e-07f

// ---------------- scratch (no allocation allowed) ----------------
__device__ float g_cos[TSEQ*(HD/2)];
__device__ float g_sin[TSEQ*(HD/2)];

// fp16 operands for projection GEMMs
__device__ __half g_xh[(size_t)MROWS*CDIM];
__device__ __half g_xl[(size_t)MROWS*CDIM];
__device__ __half g_Wqh[(size_t)CDIM*CDIM];
__device__ __half g_Wkh[(size_t)KVDIM*CDIM];
__device__ __half g_Wvh[(size_t)KVDIM*CDIM];
__device__ __half g_Woh[(size_t)CDIM*CDIM];
__device__ __half g_Ahh[(size_t)MROWS*CDIM];     // attention output (fp16)
// attention operands: Q/K bf16 3-term splits (score path), V single fp16
__device__ __nv_bfloat16 g_Qbh[(size_t)MROWS*CDIM];
__device__ __nv_bfloat16 g_Qbl[(size_t)MROWS*CDIM];
__device__ __nv_bfloat16 g_Kbh[(size_t)MROWS*KVDIM];
__device__ __nv_bfloat16 g_Kbl[(size_t)MROWS*KVDIM];
__device__ __half g_Vh[(size_t)MROWS*KVDIM];

// ---------------- small helpers ----------------
__device__ __forceinline__ uint32_t smem_u32(const void* p){
    uint32_t a;
    asm("{ .reg .u64 t; cvta.to.shared.u64 t, %1; cvt.u32.u64 %0, t; }" : "=r"(a) : "l"(p));
    return a;
}
__device__ __forceinline__ void cp16(uint32_t dst, const void* src){
    asm volatile("cp.async.cg.shared.global [%0], [%1], 16;" :: "r"(dst), "l"(src) : "memory");
}
#define CP_COMMIT() asm volatile("cp.async.commit_group;" ::: "memory")
#define CP_WAIT1()  asm volatile("cp.async.wait_group 1;" ::: "memory")

__device__ __forceinline__ void mma_bf16(float* c, const uint32_t* a, uint32_t b0, uint32_t b1){
    asm volatile(
        "mma.sync.aligned.m16n8k16.row.col.f32.bf16.bf16.f32 "
        "{%0,%1,%2,%3}, {%4,%5,%6,%7}, {%8,%9}, {%0,%1,%2,%3};"
        : "+f"(c[0]), "+f"(c[1]), "+f"(c[2]), "+f"(c[3])
        : "r"(a[0]), "r"(a[1]), "r"(a[2]), "r"(a[3]), "r"(b0), "r"(b1));
}
__device__ __forceinline__ void mma_f16(float* c, const uint32_t* a, uint32_t b0, uint32_t b1){
    asm volatile(
        "mma.sync.aligned.m16n8k16.row.col.f32.f16.f16.f32 "
        "{%0,%1,%2,%3}, {%4,%5,%6,%7}, {%8,%9}, {%0,%1,%2,%3};"
        : "+f"(c[0]), "+f"(c[1]), "+f"(c[2]), "+f"(c[3])
        : "r"(a[0]), "r"(a[1]), "r"(a[2]), "r"(a[3]), "r"(b0), "r"(b1));
}
__device__ __forceinline__ uint32_t ld2x16(const void* p){
    return *(const uint32_t*)p;
}
// bf16 split of a float pair
__device__ __forceinline__ void split_pack2(float f0, float f1, uint32_t& hi, uint32_t& lo){
    __nv_bfloat16 h0 = __float2bfloat16(f0);
    __nv_bfloat16 h1 = __float2bfloat16(f1);
    __nv_bfloat16 r0 = __float2bfloat16(f0 - __bfloat162float(h0));
    __nv_bfloat16 r1 = __float2bfloat16(f1 - __bfloat162float(h1));
    __nv_bfloat162 hh(h0, h1), ll(r0, r1);
    hi = *(uint32_t*)&hh;
    lo = *(uint32_t*)&ll;
}
// fp16 split of a float pair
__device__ __forceinline__ void split_pack2h(float f0, float f1, uint32_t& hi, uint32_t& lo){
    __half h0 = __float2half(f0);
    __half h1 = __float2half(f1);
    __half r0 = __float2half(f0 - __half2float(h0));
    __half r1 = __float2half(f1 - __half2float(h1));
    __half2 hh(h0, h1), ll(r0, r1);
    hi = *(uint32_t*)&hh;
    lo = *(uint32_t*)&ll;
}
// fp16 round of a float pair
__device__ __forceinline__ uint32_t pack2h(float f0, float f1){
    __half2 hh(__float2half(f0), __float2half(f1));
    return *(uint32_t*)&hh;
}

// ---------------- RoPE trig table ----------------
__global__ void fill_trig_kernel() {
    int i = blockIdx.x * blockDim.x + threadIdx.x;
    if (i >= TSEQ * 64) return;
    int t = i >> 6;
    int f = i & 63;
    double theta = exp(((double)(-2 * f) / 128.0) * log(10000.0));
    double ang = (double)t * theta;
    const double twopi = 6.283185307179586476925286766559;
    double k = rint(ang / twopi);
    float rf = (float)(ang - k * twopi);
    g_cos[i] = cosf(rf);
    g_sin[i] = sinf(rf);
}

// ---------------- fp32 -> fp16 hi/lo split ----------------
__global__ __launch_bounds__(256) void splith_kernel(
    const float* __restrict__ in, __half* __restrict__ hi,
    __half* __restrict__ lo, int n4)
{
    int i = blockIdx.x * blockDim.x + threadIdx.x;
    if (i >= n4) return;
    float4 v = ((const float4*)in)[i];
    uint32_t h0, l0, h1, l1;
    split_pack2h(v.x, v.y, h0, l0);
    split_pack2h(v.z, v.w, h1, l1);
    ((uint32_t*)hi)[2*i+0] = h0;
    ((uint32_t*)hi)[2*i+1] = h1;
    ((uint32_t*)lo)[2*i+0] = l0;
    ((uint32_t*)lo)[2*i+1] = l1;
}

// ---------------- fp32 -> fp16 round (weights) ----------------
__global__ __launch_bounds__(256) void roundh_kernel(
    const float* __restrict__ in, __half* __restrict__ out, int n4)
{
    int i = blockIdx.x * blockDim.x + threadIdx.x;
    if (i >= n4) return;
    float4 v = ((const float4*)in)[i];
    ((uint32_t*)out)[2*i+0] = pack2h(v.x, v.y);
    ((uint32_t*)out)[2*i+1] = pack2h(v.z, v.w);
}

// ---------------- GEMM tiling constants ----------------
#define BPAD 40
#define TEL (128*BPAD)
#define STAGE2_EL (3*TEL)              // Ah, Al, Bh
#define GEMM2_SMEM_BYTES (2*STAGE2_EL*2)   // 61440
#define STAGE1_EL (2*TEL)              // Ah, Bh (single-product)
#define GEMM1_SMEM_BYTES (2*STAGE1_EL*2)   // 40960

// ------- Fused QKV projection + RMSNorm + RoPE epilogue --------------------
__global__ __launch_bounds__(256, 2) void qkv_gemm_kernel(const float* __restrict__ gain)
{
    extern __shared__ __half smh[];
    const int tid = threadIdx.x;
    const int wid = tid >> 5, lane = tid & 31;
    const int g = lane >> 2, t4 = lane & 3;
    const int wm = (wid >> 1) * 32;
    const int wn = (wid & 1) * 64;
    const int bm = blockIdx.y * 128;
    const int ct = blockIdx.x;
    const int K = CDIM;

    const __half* Bhp;
    int nloc, Nout, mode;       // mode: 0 Q, 1 K, 2 V
    if (ct < 16)      { Bhp = g_Wqh; nloc = ct * 128;        Nout = CDIM;  mode = 0; }
    else if (ct < 20) { Bhp = g_Wkh; nloc = (ct - 16) * 128; Nout = KVDIM; mode = 1; }
    else              { Bhp = g_Wvh; nloc = (ct - 20) * 128; Nout = KVDIM; mode = 2; }

    const uint32_t smb = smem_u32(smh);
    float acc[2][8][4];
#pragma unroll
    for (int i = 0; i < 2; i++)
#pragma unroll
        for (int j = 0; j < 8; j++)
#pragma unroll
            for (int q = 0; q < 4; q++) acc[i][j][q] = 0.f;

    const int nch = K / 32;

    auto issue_chunk = [&](int c, int st) {
        const int k0 = c * 32;
        const uint32_t so = (uint32_t)st * (STAGE2_EL * 2);
        const __half* srcs[3] = {
            g_xh + (size_t)bm * K + k0, g_xl + (size_t)bm * K + k0,
            Bhp + (size_t)nloc * K + k0 };
#pragma unroll
        for (int t = 0; t < 3; t++) {
#pragma unroll
            for (int p = 0; p < 2; p++) {
                int idx = tid + p * 256;
                int r = idx >> 2;
                int c8 = (idx & 3) * 8;
                cp16(smb + so + (uint32_t)(t * TEL + r * BPAD + c8) * 2u,
                     srcs[t] + (size_t)r * K + c8);
            }
        }
    };

    issue_chunk(0, 0); CP_COMMIT();
    issue_chunk(1, 1); CP_COMMIT();

    for (int c = 0; c < nch; c++) {
        CP_WAIT1();
        __syncthreads();
        const int st = c & 1;
        const __half* Ahs = smh + st * STAGE2_EL;
        const __half* Als = Ahs + TEL;
        const __half* Bhs = Als + TEL;

#pragma unroll
        for (int kk = 0; kk < 32; kk += 16) {
            uint32_t ah[2][4], al[2][4];
#pragma unroll
            for (int mt = 0; mt < 2; mt++) {
                const __half* ap = Ahs + (wm + mt * 16 + g) * BPAD + kk + 2 * t4;
                ah[mt][0] = ld2x16(ap);
                ah[mt][1] = ld2x16(ap + 8 * BPAD);
                ah[mt][2] = ld2x16(ap + 8);
                ah[mt][3] = ld2x16(ap + 8 * BPAD + 8);
                const __half* aq = Als + (wm + mt * 16 + g) * BPAD + kk + 2 * t4;
                al[mt][0] = ld2x16(aq);
                al[mt][1] = ld2x16(aq + 8 * BPAD);
                al[mt][2] = ld2x16(aq + 8);
                al[mt][3] = ld2x16(aq + 8 * BPAD + 8);
            }
#pragma unroll
            for (int nt = 0; nt < 8; nt++) {
                const __half* bp = Bhs + (wn + nt * 8 + g) * BPAD + kk + 2 * t4;
                uint32_t b0 = ld2x16(bp);
                uint32_t b1 = ld2x16(bp + 8);
                mma_f16(acc[0][nt], ah[0], b0, b1);
                mma_f16(acc[1][nt], ah[1], b0, b1);
                mma_f16(acc[0][nt], al[0], b0, b1);
                mma_f16(acc[1][nt], al[1], b0, b1);
            }
        }
        __syncthreads();
        if (c + 2 < nch) issue_chunk(c + 2, st);
        CP_COMMIT();
    }

    if (mode == 2) {
        // ---- V epilogue: fp16 round, direct store ----
#pragma unroll
        for (int mt = 0; mt < 2; mt++) {
            int r0 = bm + wm + mt * 16 + g;
#pragma unroll
            for (int nt = 0; nt < 8; nt++) {
                int col = nloc + wn + nt * 8 + 2 * t4;
                *(uint32_t*)(g_Vh + (size_t)r0 * Nout + col) =
                    pack2h(acc[mt][nt][0], acc[mt][nt][1]);
                *(uint32_t*)(g_Vh + (size_t)(r0 + 8) * Nout + col) =
                    pack2h(acc[mt][nt][2], acc[mt][nt][3]);
            }
        }
    } else {
        // ---- Q/K epilogue: RMSNorm + RoPE + bf16 hi/lo split ----
        __syncthreads();
        float* sums = (float*)smh;            // [2][128]
#pragma unroll
        for (int mt = 0; mt < 2; mt++) {
            float p0 = 0.f, p1 = 0.f;
#pragma unroll
            for (int nt = 0; nt < 8; nt++) {
                p0 += acc[mt][nt][0] * acc[mt][nt][0] + acc[mt][nt][1] * acc[mt][nt][1];
                p1 += acc[mt][nt][2] * acc[mt][nt][2] + acc[mt][nt][3] * acc[mt][nt][3];
            }
            p0 += __shfl_xor_sync(0xffffffffu, p0, 1);
            p0 += __shfl_xor_sync(0xffffffffu, p0, 2);
            p1 += __shfl_xor_sync(0xffffffffu, p1, 1);
            p1 += __shfl_xor_sync(0xffffffffu, p1, 2);
            if (t4 == 0) {
                sums[(wid & 1) * 128 + wm + mt * 16 + g]     = p0;
                sums[(wid & 1) * 128 + wm + mt * 16 + g + 8] = p1;
            }
        }
        __syncthreads();

        const float gmul = (mode == 0) ? gain[ct] * 0.08838834764831845f : 1.0f;
        __nv_bfloat16* dsth = (mode == 0) ? g_Qbh : g_Kbh;
        __nv_bfloat16* dstl = (mode == 0) ? g_Qbl : g_Kbl;
#pragma unroll
        for (int mt = 0; mt < 2; mt++) {
#pragma unroll
            for (int rr = 0; rr < 2; rr++) {
                int lrow = wm + mt * 16 + g + rr * 8;
                int grow = bm + lrow;
                int t = grow & (TSEQ - 1);
                float ss = sums[lrow] + sums[128 + lrow];
                float gm = rsqrtf(ss * (1.0f / 128.0f) + EPSF) * gmul;
#pragma unroll
                for (int nt = 0; nt < 8; nt++) {
                    float xe = acc[mt][nt][rr * 2];
                    float xo = acc[mt][nt][rr * 2 + 1];
                    int d = ((wn + nt * 8) >> 1) + t4;
                    float c = g_cos[t * 64 + d];
                    float s = g_sin[t * 64 + d];
                    float re = (xe * c - xo * s) * gm;
                    float ro = (xe * s + xo * c) * gm;
                    uint32_t hi, lo;
                    split_pack2(re, ro, hi, lo);
                    int col = nloc + wn + nt * 8 + 2 * t4;
                    *(uint32_t*)(dsth + (size_t)grow * Nout + col) = hi;
                    *(uint32_t*)(dstl + (size_t)grow * Nout + col) = lo;
                }
            }
        }
    }
}

// ------- fp16 single-product GEMM (O projection): C = Ah * Bh^T ------------
__global__ __launch_bounds__(256, 2) void f16_gemm1_kernel(
    const __half* __restrict__ Ahp, const __half* __restrict__ Bhp,
    float* __restrict__ C, int M, int N, int K)
{
    extern __shared__ __half smh[];
    const int tid = threadIdx.x;
    const int wid = tid >> 5, lane = tid & 31;
    const int g = lane >> 2, t4 = lane & 3;
    const int wm = (wid >> 1) * 32;
    const int wn = (wid & 1) * 64;
    const int bm = blockIdx.y * 128, bn = blockIdx.x * 128;

    const uint32_t smb = smem_u32(smh);
    float acc[2][8][4];
#pragma unroll
    for (int i = 0; i < 2; i++)
#pragma unroll
        for (int j = 0; j < 8; j++)
#pragma unroll
            for (int q = 0; q < 4; q++) acc[i][j][q] = 0.f;

    const int nch = K / 32;

    auto issue_chunk = [&](int c, int st) {
        const int k0 = c * 32;
        const uint32_t so = (uint32_t)st * (STAGE1_EL * 2);
        const __half* srcs[2] = {
            Ahp + (size_t)bm * K + k0, Bhp + (size_t)bn * K + k0 };
#pragma unroll
        for (int t = 0; t < 2; t++) {
#pragma unroll
            for (int p = 0; p < 2; p++) {
                int idx = tid + p * 256;
                int r = idx >> 2;
                int c8 = (idx & 3) * 8;
                cp16(smb + so + (uint32_t)(t * TEL + r * BPAD + c8) * 2u,
                     srcs[t] + (size_t)r * K + c8);
            }
        }
    };

    issue_chunk(0, 0); CP_COMMIT();
    issue_chunk(1, 1); CP_COMMIT();

    for (int c = 0; c < nch; c++) {
        CP_WAIT1();
        __syncthreads();
        const int st = c & 1;
        const __half* Ahs = smh + st * STAGE1_EL;
        const __half* Bhs = Ahs + TEL;

#pragma unroll
        for (int kk = 0; kk < 32; kk += 16) {
            uint32_t ah[2][4];
#pragma unroll
            for (int mt = 0; mt < 2; mt++) {
                const __half* ap = Ahs + (wm + mt * 16 + g) * BPAD + kk + 2 * t4;
                ah[mt][0] = ld2x16(ap);
                ah[mt][1] = ld2x16(ap + 8 * BPAD);
                ah[mt][2] = ld2x16(ap + 8);
                ah[mt][3] = ld2x16(ap + 8 * BPAD + 8);
            }
#pragma unroll
            for (int nt = 0; nt < 8; nt++) {
                const __half* bp = Bhs + (wn + nt * 8 + g) * BPAD + kk + 2 * t4;
                uint32_t b0 = ld2x16(bp);
                uint32_t b1 = ld2x16(bp + 8);
                mma_f16(acc[0][nt], ah[0], b0, b1);
                mma_f16(acc[1][nt], ah[1], b0, b1);
            }
        }
        __syncthreads();
        if (c + 2 < nch) issue_chunk(c + 2, st);
        CP_COMMIT();
    }

#pragma unroll
    for (int mt = 0; mt < 2; mt++) {
        int r0 = bm + wm + mt * 16 + g;
#pragma unroll
        for (int nt = 0; nt < 8; nt++) {
            int col = bn + wn + nt * 8 + 2 * t4;
            float2 w0 = make_float2(acc[mt][nt][0], acc[mt][nt][1]);
            float2 w1 = make_float2(acc[mt][nt][2], acc[mt][nt][3]);
            *(float2*)(C + (size_t)r0 * N + col) = w0;
            *(float2*)(C + (size_t)(r0 + 8) * N + col) = w1;
        }
    }
}

// -------- Tensor-core flash attention, causal, GQA ------------------------
// S: bf16 3-term.  PV: fp16 single-product (P fp16-rounded, V fp16).
#define KPAD 136
#define VTPAD 70
#define ATT_Q_EL (64*KPAD)
#define ATT_VT_EL (128*VTPAD)
#define ATT_SMEM_BYTES ((4*ATT_Q_EL)*2 + ATT_VT_EL*2)   // 87552

__global__ __launch_bounds__(128, 2) void attn_tc_kernel() {
    extern __shared__ __nv_bfloat16 sma[];
    __nv_bfloat16* Qh  = sma;
    __nv_bfloat16* Ql  = Qh + ATT_Q_EL;
    __nv_bfloat16* Kh  = Ql + ATT_Q_EL;
    __nv_bfloat16* Kl  = Kh + ATT_Q_EL;
    __half*        Vt  = (__half*)(Kl + ATT_Q_EL);

    const int qt = (int)(gridDim.x - 1u - blockIdx.x);   // long CTAs first
    const int h = blockIdx.y, b = blockIdx.z;
    const int kvh = h >> 2;
    const int tid = threadIdx.x, wid = tid >> 5, lane = tid & 31;
    const int g = lane >> 2, t4 = lane & 3;
    const int q0 = qt * 64, wq = wid * 16;

    const __nv_bfloat16* Qhb = g_Qbh + ((size_t)(b * TSEQ + q0)) * CDIM + h * HD;
    const __nv_bfloat16* Qlb = g_Qbl + ((size_t)(b * TSEQ + q0)) * CDIM + h * HD;
    const __nv_bfloat16* Khb = g_Kbh + ((size_t)b * TSEQ) * KVDIM + kvh * HD;
    const __nv_bfloat16* Klb = g_Kbl + ((size_t)b * TSEQ) * KVDIM + kvh * HD;
    const __half*        Vhb = g_Vh  + ((size_t)b * TSEQ) * KVDIM + kvh * HD;

    for (int f = tid; f < 1024; f += 128) {
        int r = f >> 4, c8 = (f & 15) * 8;
        *(uint4*)(Qh + r * KPAD + c8) = *(const uint4*)(Qhb + (size_t)r * CDIM + c8);
        *(uint4*)(Ql + r * KPAD + c8) = *(const uint4*)(Qlb + (size_t)r * CDIM + c8);
    }

    float o[16][4];
#pragma unroll
    for (int i = 0; i < 16; i++)
#pragma unroll
        for (int j = 0; j < 4; j++) o[i][j] = 0.f;
    float m0 = -1e30f, m1 = -1e30f, l0 = 0.f, l1 = 0.f;

    for (int kt = 0; kt <= qt; kt++) {
        const int k0 = kt * 64;
        __syncthreads();
        for (int f = tid; f < 1024; f += 128) {
            int r = f >> 4, c8 = (f & 15) * 8;
            *(uint4*)(Kh + r * KPAD + c8) =
                *(const uint4*)(Khb + (size_t)(k0 + r) * KVDIM + c8);
            *(uint4*)(Kl + r * KPAD + c8) =
                *(const uint4*)(Klb + (size_t)(k0 + r) * KVDIM + c8);
        }
        for (int f = tid; f < 1024; f += 128) {
            int r = f >> 4, c8 = (f & 15) * 8;
            uint4 vh = *(const uint4*)(Vhb + (size_t)(k0 + r) * KVDIM + c8);
            __half th[8];
            *(uint4*)th = vh;
#pragma unroll
            for (int j = 0; j < 8; j++)
                Vt[(c8 + j) * VTPAD + r] = th[j];
        }
        __syncthreads();

        // ---- S = Q K^T (3-term split, fp32 accum) ----
        float s[8][4];
#pragma unroll
        for (int i = 0; i < 8; i++)
#pragma unroll
            for (int j = 0; j < 4; j++) s[i][j] = 0.f;

#pragma unroll
        for (int kk = 0; kk < 128; kk += 16) {
            uint32_t ah[4], al[4];
            const __nv_bfloat16* ap = Qh + (wq + g) * KPAD + kk + 2 * t4;
            ah[0] = ld2x16(ap);
            ah[1] = ld2x16(ap + 8 * KPAD);
            ah[2] = ld2x16(ap + 8);
            ah[3] = ld2x16(ap + 8 * KPAD + 8);
            const __nv_bfloat16* aq = Ql + (wq + g) * KPAD + kk + 2 * t4;
            al[0] = ld2x16(aq);
            al[1] = ld2x16(aq + 8 * KPAD);
            al[2] = ld2x16(aq + 8);
            al[3] = ld2x16(aq + 8 * KPAD + 8);
#pragma unroll
            for (int nt = 0; nt < 8; nt++) {
                const __nv_bfloat16* bp = Kh + (nt * 8 + g) * KPAD + kk + 2 * t4;
                uint32_t b0h = ld2x16(bp), b1h = ld2x16(bp + 8);
                const __nv_bfloat16* bq = Kl + (nt * 8 + g) * KPAD + kk + 2 * t4;
                uint32_t b0l = ld2x16(bq), b1l = ld2x16(bq + 8);
                mma_bf16(s[nt], ah, b0h, b1h);
                mma_bf16(s[nt], ah, b0l, b1l);
                mma_bf16(s[nt], al, b0h, b1h);
            }
        }

        // ---- causal mask on diagonal tile ----
        if (kt == qt) {
            int qr0 = q0 + wq + g, qr1 = qr0 + 8;
#pragma unroll
            for (int nt = 0; nt < 8; nt++) {
                int kc = k0 + nt * 8 + 2 * t4;
                if (kc     > qr0) s[nt][0] = -1e30f;
                if (kc + 1 > qr0) s[nt][1] = -1e30f;
                if (kc     > qr1) s[nt][2] = -1e30f;
                if (kc + 1 > qr1) s[nt][3] = -1e30f;
            }
        }

        // ---- online softmax ----
        float mx0 = -1e30f, mx1 = -1e30f;
#pragma unroll
        for (int nt = 0; nt < 8; nt++) {
            mx0 = fmaxf(mx0, fmaxf(s[nt][0], s[nt][1]));
            mx1 = fmaxf(mx1, fmaxf(s[nt][2], s[nt][3]));
        }
        mx0 = fmaxf(mx0, __shfl_xor_sync(0xffffffffu, mx0, 1));
        mx0 = fmaxf(mx0, __shfl_xor_sync(0xffffffffu, mx0, 2));
        mx1 = fmaxf(mx1, __shfl_xor_sync(0xffffffffu, mx1, 1));
        mx1 = fmaxf(mx1, __shfl_xor_sync(0xffffffffu, mx1, 2));
        float mn0 = fmaxf(m0, mx0), mn1 = fmaxf(m1, mx1);
        float cr0 = __expf(m0 - mn0), cr1 = __expf(m1 - mn1);
        float sum0 = 0.f, sum1 = 0.f;
#pragma unroll
        for (int nt = 0; nt < 8; nt++) {
            s[nt][0] = __expf(s[nt][0] - mn0);
            s[nt][1] = __expf(s[nt][1] - mn0);
            s[nt][2] = __expf(s[nt][2] - mn1);
            s[nt][3] = __expf(s[nt][3] - mn1);
            sum0 += s[nt][0] + s[nt][1];
            sum1 += s[nt][2] + s[nt][3];
        }
        sum0 += __shfl_xor_sync(0xffffffffu, sum0, 1);
        sum0 += __shfl_xor_sync(0xffffffffu, sum0, 2);
        sum1 += __shfl_xor_sync(0xffffffffu, sum1, 1);
        sum1 += __shfl_xor_sync(0xffffffffu, sum1, 2);
        l0 = l0 * cr0 + sum0; m0 = mn0;
        l1 = l1 * cr1 + sum1; m1 = mn1;
#pragma unroll
        for (int nt = 0; nt < 16; nt++) {
            o[nt][0] *= cr0; o[nt][1] *= cr0;
            o[nt][2] *= cr1; o[nt][3] *= cr1;
        }

        // ---- O += P V (fp16 single-product; P rounded from S registers) ----
#pragma unroll
        for (int jp = 0; jp < 4; jp++) {
            uint32_t pa[4];
            pa[0] = pack2h(s[2*jp  ][0], s[2*jp  ][1]);
            pa[1] = pack2h(s[2*jp  ][2], s[2*jp  ][3]);
            pa[2] = pack2h(s[2*jp+1][0], s[2*jp+1][1]);
            pa[3] = pack2h(s[2*jp+1][2], s[2*jp+1][3]);
#pragma unroll
            for (int nt = 0; nt < 16; nt++) {
                const __half* vp = Vt + (nt * 8 + g) * VTPAD + jp * 16 + 2 * t4;
                uint32_t v0 = ld2x16(vp), v1 = ld2x16(vp + 8);
                mma_f16(o[nt], pa, v0, v1);
            }
        }
    }

    // ---- epilogue: normalize, round to fp16, store ----
    float inv0 = 1.0f / l0, inv1 = 1.0f / l1;
    size_t row0 = (size_t)(b * TSEQ + q0 + wq + g) * CDIM + h * HD;
    size_t row1 = row0 + (size_t)8 * CDIM;
#pragma unroll
    for (int nt = 0; nt < 16; nt++) {
        int col = nt * 8 + 2 * t4;
        *(uint32_t*)(g_Ahh + row0 + col) = pack2h(o[nt][0] * inv0, o[nt][1] * inv0);
        *(uint32_t*)(g_Ahh + row1 + col) = pack2h(o[nt][2] * inv1, o[nt][3] * inv1);
    }
}

// ---------------- launch ----------------
extern "C" void kernel_launch(void* const* d_in, const int* in_sizes, int n_in,
                              void* d_out, int out_size) {
    const float* x    = (const float*)d_in[0];
    const float* Wq   = (const float*)d_in[1];
    const float* Wk   = (const float*)d_in[2];
    const float* Wv   = (const float*)d_in[3];
    const float* Wo   = (const float*)d_in[4];
    const float* gain = (const float*)d_in[5];
    float* out = (float*)d_out;

    __half *xh, *xl, *wqh, *wkh, *wvh, *woh, *ah;
    cudaGetSymbolAddress((void**)&xh, g_xh);   cudaGetSymbolAddress((void**)&xl, g_xl);
    cudaGetSymbolAddress((void**)&wqh, g_Wqh);
    cudaGetSymbolAddress((void**)&wkh, g_Wkh);
    cudaGetSymbolAddress((void**)&wvh, g_Wvh);
    cudaGetSymbolAddress((void**)&woh, g_Woh);
    cudaGetSymbolAddress((void**)&ah, g_Ahh);

    cudaFuncSetAttribute(qkv_gemm_kernel, cudaFuncAttributeMaxDynamicSharedMemorySize,
                         GEMM2_SMEM_BYTES);
    cudaFuncSetAttribute(f16_gemm1_kernel, cudaFuncAttributeMaxDynamicSharedMemorySize,
                         GEMM1_SMEM_BYTES);
    cudaFuncSetAttribute(attn_tc_kernel, cudaFuncAttributeMaxDynamicSharedMemorySize,
                         ATT_SMEM_BYTES);

    fill_trig_kernel<<<(TSEQ * 64 + 255) / 256, 256>>>();

    // operand prep
    splith_kernel<<<(MROWS*CDIM/4 + 255)/256, 256>>>(x, xh, xl, MROWS*CDIM/4);
    roundh_kernel<<<(CDIM*CDIM/4 + 255)/256, 256>>>(Wq, wqh, CDIM*CDIM/4);
    roundh_kernel<<<(KVDIM*CDIM/4 + 255)/256, 256>>>(Wk, wkh, KVDIM*CDIM/4);
    roundh_kernel<<<(KVDIM*CDIM/4 + 255)/256, 256>>>(Wv, wvh, KVDIM*CDIM/4);
    roundh_kernel<<<(CDIM*CDIM/4 + 255)/256, 256>>>(Wo, woh, CDIM*CDIM/4);

    // fused QKV projections + norm + rope (Q/K bf16 splits; V fp16 direct)
    dim3 gqkv(24, MROWS / 128);
    qkv_gemm_kernel<<<gqkv, 256, GEMM2_SMEM_BYTES>>>(gain);

    // tensor-core flash attention -> fp16 A
    dim3 ga(TSEQ / 64, NH, BATCH);
    attn_tc_kernel<<<ga, 128, ATT_SMEM_BYTES>>>();

    // O projection (fp16 single-product)
    dim3 gq(CDIM / 128, MROWS / 128);
    f16_gemm1_kernel<<<gq, 256, GEMM1_SMEM_BYTES>>>(ah, woh, out, MROWS, CDIM, CDIM);
}